// round 9
// baseline (speedup 1.0000x reference)
#include <cuda_runtime.h>
#include <cstdint>

#define N_ENT   100000
#define D       128
#define NB_SCAN 49

// ---------------- scratch (static, no allocs) ----------------
__device__ float4 g_neigh4[(size_t)N_ENT * 32];
__device__ float2 g_Wsw[128 * 128];   // [c][slot]: k-pair granules, slot = kp ^ (c&15)
__device__ int    g_cnt[N_ENT];
__device__ int    g_start[N_ENT + 1];
__device__ int    g_head[N_ENT];
__device__ int    g_bsum[64];
__device__ int    g_boff[64];
__device__ float2 g_edge[1600000];

// ---------------- f32x2 helpers ----------------
__device__ __forceinline__ unsigned long long ffma2(unsigned long long a,
                                                    unsigned long long b,
                                                    unsigned long long c) {
    unsigned long long d;
    asm("fma.rn.f32x2 %0, %1, %2, %3;" : "=l"(d) : "l"(a), "l"(b), "l"(c));
    return d;
}
__device__ __forceinline__ void unpack2(unsigned long long v, float& x, float& y) {
    asm("mov.b64 {%0, %1}, %2;" : "=f"(x), "=f"(y) : "l"(v));
}

// ---------------- prep: zero cnt + swizzled k-pair weights ----------------
// Wcat[c][k] = k<128 ? Ws[c][k] : Wn[c][k-128]; granule kp = (Wcat[c][2kp], Wcat[c][2kp+1])
__global__ void k_prep(const float* __restrict__ Ws, const float* __restrict__ Wn, int n) {
    int i = blockIdx.x * blockDim.x + threadIdx.x;
    if (i < n) g_cnt[i] = 0;
    if (i < 128 * 128) {
        int c = i >> 7, kp = i & 127;
        int k = kp * 2;
        float2 v;
        if (k < 128) v = *(const float2*)(Ws + c * 128 + k);
        else         v = *(const float2*)(Wn + c * 128 + (k - 128));
        g_Wsw[c * 128 + (kp ^ (c & 15))] = v;
    }
}

// ---------------- CSR build ----------------
__global__ void k_hist(const int* __restrict__ rows, int E) {
    int i = blockIdx.x * blockDim.x + threadIdx.x;
    if (i < E) atomicAdd(&g_cnt[rows[i]], 1);
}
__global__ void k_scan1(int n) {
    __shared__ int ss[256];
    int b = blockIdx.x, t = threadIdx.x;
    int base = b * 2048 + t * 8;
    int loc[8], s = 0;
#pragma unroll
    for (int i = 0; i < 8; i++) {
        int idx = base + i;
        loc[i] = (idx < n) ? g_cnt[idx] : 0;
        s += loc[i];
    }
    ss[t] = s;
    __syncthreads();
    for (int off = 1; off < 256; off <<= 1) {
        int v = 0;
        if (t >= off) v = ss[t - off];
        __syncthreads();
        if (t >= off) ss[t] += v;
        __syncthreads();
    }
    int excl = ss[t] - s;
#pragma unroll
    for (int i = 0; i < 8; i++) {
        int idx = base + i;
        if (idx < n) g_start[idx] = excl;
        excl += loc[i];
    }
    if (t == 255) g_bsum[b] = ss[255];
}
__global__ void k_scan2(int nb) {
    __shared__ int ss[64];
    int t = threadIdx.x;
    int v = (t < nb) ? g_bsum[t] : 0;
    ss[t] = v;
    __syncthreads();
    for (int off = 1; off < 64; off <<= 1) {
        int u = 0;
        if (t >= off) u = ss[t - off];
        __syncthreads();
        if (t >= off) ss[t] += u;
        __syncthreads();
    }
    if (t < nb) g_boff[t] = ss[t] - v;
}
__global__ void k_scan3(int n, int E) {
    int i = blockIdx.x * blockDim.x + threadIdx.x;
    if (i < n) {
        int v = g_start[i] + g_boff[i >> 11];
        g_start[i] = v;
        g_head[i] = v;
    }
    if (i == 0) g_start[n] = E;
}
__global__ void k_scatter(const int* __restrict__ rows, const int* __restrict__ cols,
                          const float* __restrict__ vals, int E) {
    int i = blockIdx.x * blockDim.x + threadIdx.x;
    if (i < E) {
        int pos = atomicAdd(&g_head[rows[i]], 1);
        g_edge[pos] = make_float2(__int_as_float(cols[i]), vals[i]);
    }
}
__global__ void k_spmm(const float4* __restrict__ embs, int n) {
    int w = (int)((blockIdx.x * blockDim.x + threadIdx.x) >> 5);
    int lane = threadIdx.x & 31;
    if (w >= n) return;
    int s = g_start[w], t = g_start[w + 1];
    float4 acc = make_float4(0.f, 0.f, 0.f, 0.f);
    int e = s;
    for (; e + 4 <= t; e += 4) {
        float2 e0 = g_edge[e], e1 = g_edge[e + 1], e2 = g_edge[e + 2], e3 = g_edge[e + 3];
        float4 r0 = embs[(size_t)__float_as_int(e0.x) * 32 + lane];
        float4 r1 = embs[(size_t)__float_as_int(e1.x) * 32 + lane];
        float4 r2 = embs[(size_t)__float_as_int(e2.x) * 32 + lane];
        float4 r3 = embs[(size_t)__float_as_int(e3.x) * 32 + lane];
        acc.x += e0.y * r0.x + e1.y * r1.x + e2.y * r2.x + e3.y * r3.x;
        acc.y += e0.y * r0.y + e1.y * r1.y + e2.y * r2.y + e3.y * r3.y;
        acc.z += e0.y * r0.z + e1.y * r1.z + e2.y * r2.z + e3.y * r3.z;
        acc.w += e0.y * r0.w + e1.y * r1.w + e2.y * r2.w + e3.y * r3.w;
    }
    for (; e < t; e++) {
        float2 ed = g_edge[e];
        float4 r = embs[(size_t)__float_as_int(ed.x) * 32 + lane];
        acc.x += ed.y * r.x; acc.y += ed.y * r.y;
        acc.z += ed.y * r.z; acc.w += ed.y * r.w;
    }
    g_neigh4[(size_t)w * 32 + lane] = acc;
}

// ---------------- GEMM: K-paired FFMA2, 64x128 tiles, persistent ----------------
// out = leaky( [x | neigh] @ Wcat^T + bs + bn ), K = 256 (128 k-pairs)
// SMEM: sW [128 c][1KB row, swizzled kp slots] = 128KB; sA [64 r][1KB row] = 64KB
#define GSM_W    0
#define GSM_A    131072
#define GSM_TOT  (131072 + 65536)

__global__ __launch_bounds__(256, 1)
void k_gemm(const float* __restrict__ x,
            const float* __restrict__ bs,
            const float* __restrict__ bn,
            float* __restrict__ out, int N) {
    extern __shared__ char sm[];
    char* sW = sm + GSM_W;
    char* sA = sm + GSM_A;
    const float* neigh = (const float*)g_neigh4;
    int tid = threadIdx.x, lane = tid & 31, wid = tid >> 5;

    // per-thread bias for cols lane + 32j
    float bb[4];
#pragma unroll
    for (int j = 0; j < 4; j++) {
        int c = lane + 32 * j;
        bb[j] = bs[c] + bn[c];
    }
    // W: straight 128KB copy (pre-swizzled in gmem)
    {
        const float4* src = (const float4*)g_Wsw;
        float4* dst = (float4*)sW;
#pragma unroll
        for (int i = 0; i < 32; i++) dst[tid + i * 256] = src[tid + i * 256];
    }

    int ntiles = (N + 63) >> 6;
    for (int tile = blockIdx.x; tile < ntiles; tile += gridDim.x) {
        int row0 = tile << 6;
        __syncthreads();   // prev compute done before refill
        // A tile: 64 rows x 256 k (x | neigh), r-major, coalesced STS.128
#pragma unroll
        for (int i = 0; i < 16; i++) {
            int idx = i * 256 + tid, r = idx >> 6, kq = idx & 63;
            int gr = row0 + r;
            float4 v = make_float4(0.f, 0.f, 0.f, 0.f);
            if (gr < N)
                v = (kq < 32) ? *(const float4*)(x + (size_t)gr * 128 + kq * 4)
                              : g_neigh4[(size_t)gr * 32 + (kq - 32)];
            *(float4*)(sA + r * 1024 + (kq << 4)) = v;
        }
        __syncthreads();

        unsigned long long acc[8][4];
#pragma unroll
        for (int i = 0; i < 8; i++)
#pragma unroll
            for (int j = 0; j < 4; j++) acc[i][j] = 0ull;

        const char* aw = sA + wid * 8192;          // this warp's 8 rows
        const char* wl = sW + lane * 1024;          // this lane's base col
        uint32_t ksw = ((uint32_t)(lane & 15)) << 3;
#pragma unroll 2
        for (int kp = 0; kp < 128; kp++) {
            unsigned long long a[8], w[4];
            uint32_t ko = (uint32_t)kp << 3;
#pragma unroll
            for (int i = 0; i < 8; i++)
                a[i] = *(const unsigned long long*)(aw + i * 1024 + ko);   // broadcast
            uint32_t wo = ko ^ ksw;
#pragma unroll
            for (int j = 0; j < 4; j++)
                w[j] = *(const unsigned long long*)(wl + j * 32768 + wo);  // conflict-free
#pragma unroll
            for (int i = 0; i < 8; i++)
#pragma unroll
                for (int j = 0; j < 4; j++) acc[i][j] = ffma2(a[i], w[j], acc[i][j]);
        }

        // epilogue: sum halves + bias + leaky, coalesced STG.32
#pragma unroll
        for (int i = 0; i < 8; i++) {
            int gr = row0 + wid * 8 + i;
            if (gr >= N) continue;
            float* op = out + (size_t)gr * 128;
#pragma unroll
            for (int j = 0; j < 4; j++) {
                float lo, hi;
                unpack2(acc[i][j], lo, hi);
                float t = lo + hi + bb[j];
                op[lane + 32 * j] = t > 0.f ? t : 0.01f * t;
            }
        }
    }
}

extern "C" void kernel_launch(void* const* d_in, const int* in_sizes, int n_in,
                              void* d_out, int out_size) {
    const float* embs = (const float*)d_in[0];
    const int*   rows = (const int*)d_in[1];
    const int*   cols = (const int*)d_in[2];
    const float* vals = (const float*)d_in[3];
    const float* Ws   = (const float*)d_in[4];
    const float* bs   = (const float*)d_in[5];
    const float* Wn   = (const float*)d_in[6];
    const float* bn   = (const float*)d_in[7];
    float* out = (float*)d_out;

    int N = in_sizes[0] / D;
    int E = in_sizes[1];

    cudaFuncSetAttribute(k_gemm, cudaFuncAttributeMaxDynamicSharedMemorySize, GSM_TOT);

    k_prep<<<(N + 255) / 256, 256>>>(Ws, Wn, N);
    k_hist<<<(E + 255) / 256, 256>>>(rows, E);
    k_scan1<<<NB_SCAN, 256>>>(N);
    k_scan2<<<1, 64>>>(NB_SCAN);
    k_scan3<<<(N + 255) / 256, 256>>>(N, E);
    k_scatter<<<(E + 255) / 256, 256>>>(rows, cols, vals, E);
    k_spmm<<<(N + 7) / 8, 256>>>((const float4*)embs, N);
    k_gemm<<<148, 256, GSM_TOT>>>(embs, bs, bn, out, N);
}